// round 2
// baseline (speedup 1.0000x reference)
#include <cuda_runtime.h>

#define NN 100000
#define EE 3200000
#define HH 64

// ---------------- scratch (static device globals; no allocation) ----------------
__device__ int   g_deg[NN];
__device__ int   g_rowptr[NN + 1];
__device__ int   g_cursor[NN];
__device__ int   g_col[EE];
__device__ float g_dinv[NN];
__device__ __align__(16) float g_bufA[NN * HH];
__device__ __align__(16) float g_bufB[NN * HH];
__device__ int   g_part[128];
__device__ int   g_is64;

// ---------------- edge dtype detection ----------------
// If edge_index is int64 (little-endian, values < 2^31), every odd int32 word is 0.
// If int32, odd words are real node ids (nonzero with overwhelming probability).
__global__ void k_detect(const int* __restrict__ ei32) {
    if (blockIdx.x == 0 && threadIdx.x == 0) {
        int z = 0;
        for (int i = 1; i < 4096; i += 2) z += (ei32[i] == 0);
        g_is64 = (z >= 1536) ? 1 : 0;
    }
}

__device__ __forceinline__ int edge_at(const void* ei, size_t idx) {
    if (g_is64) return (int)((const long long*)ei)[idx];
    return ((const int*)ei)[idx];
}

// ---------------- CSR build ----------------
__global__ void k_zero() {
    int i = blockIdx.x * blockDim.x + threadIdx.x;
    if (i < NN) g_deg[i] = 0;
}

__global__ void k_deg(const void* __restrict__ ei) {
    int e = blockIdx.x * blockDim.x + threadIdx.x;
    if (e < EE) {
        int dst = edge_at(ei, (size_t)EE + e);
        atomicAdd(&g_deg[dst], 1);
    }
}

// exclusive scan of g_deg -> g_rowptr, 1024 elems/block (256 thr x 4)
__global__ void k_scan1() {
    __shared__ int s[256];
    int t = threadIdx.x;
    int base = blockIdx.x * 1024 + t * 4;
    int v[4]; int sum = 0;
#pragma unroll
    for (int r = 0; r < 4; r++) { int i = base + r; v[r] = (i < NN) ? g_deg[i] : 0; sum += v[r]; }
    s[t] = sum;
    __syncthreads();
    for (int off = 1; off < 256; off <<= 1) {
        int x = (t >= off) ? s[t - off] : 0;
        __syncthreads();
        s[t] += x;
        __syncthreads();
    }
    int run = s[t] - sum;  // exclusive prefix within block
#pragma unroll
    for (int r = 0; r < 4; r++) { int i = base + r; if (i < NN) g_rowptr[i] = run; run += v[r]; }
    if (t == 255) g_part[blockIdx.x] = s[255];
}

__global__ void k_scan2(int nb) {
    __shared__ int s[128];
    int t = threadIdx.x;
    int v = (t < nb) ? g_part[t] : 0;
    s[t] = v;
    __syncthreads();
    for (int off = 1; off < 128; off <<= 1) {
        int x = (t >= off) ? s[t - off] : 0;
        __syncthreads();
        s[t] += x;
        __syncthreads();
    }
    if (t < nb) g_part[t] = s[t] - v;  // exclusive
}

__global__ void k_scan3() {
    int t = threadIdx.x;
    int base = blockIdx.x * 1024 + t * 4;
    int off = g_part[blockIdx.x];
#pragma unroll
    for (int r = 0; r < 4; r++) {
        int i = base + r;
        if (i < NN) {
            int rp = g_rowptr[i] + off;
            g_rowptr[i] = rp;
            g_cursor[i] = rp;
            g_dinv[i] = rsqrtf((float)g_deg[i] + 1.0f);
        }
    }
    if (blockIdx.x == 0 && t == 0) g_rowptr[NN] = EE;
}

__global__ void k_fill(const void* __restrict__ ei) {
    int e = blockIdx.x * blockDim.x + threadIdx.x;
    if (e < EE) {
        int src = edge_at(ei, e);
        int dst = edge_at(ei, (size_t)EE + e);
        int p = atomicAdd(&g_cursor[dst], 1);
        g_col[p] = src;
    }
}

// ---------------- fused encoders + GCN0 linear : hs0 = dinv .* (relu-concat @ W0) ----------------
// block = 256 threads, processes 64 nodes. Dynamic smem ~116KB.
__global__ void __launch_bounds__(256) k_enc0(
    const float* __restrict__ xf, const float* __restrict__ xw, const float* __restrict__ xt,
    const float* __restrict__ wf, const float* __restrict__ bfir,
    const float* __restrict__ ww, const float* __restrict__ bwea,
    const float* __restrict__ wt, const float* __restrict__ bter,
    const float* __restrict__ W0)
{
    extern __shared__ __align__(16) float sm[];
    float* Ws   = sm;            // 192*64 = 12288
    float* Wenc = Ws + 12288;    // 30*64  = 1920
    float* Benc = Wenc + 1920;   // 192
    float* xs   = Benc + 192;    // 64*196 = 12544
    float* raw  = xs + 12544;    // 64*32  = 2048
    const int t = threadIdx.x;

    for (int i = t; i < 12288; i += 256) Ws[i] = W0[i];
    for (int i = t; i < 512;  i += 256) Wenc[i] = wf[i];
    for (int i = t; i < 768;  i += 256) Wenc[512 + i] = ww[i];
    for (int i = t; i < 640;  i += 256) Wenc[1280 + i] = wt[i];
    if (t < 64) { Benc[t] = bfir[t]; Benc[64 + t] = bwea[t]; Benc[128 + t] = bter[t]; }

    const int n0g = blockIdx.x * 64;
    for (int i = t; i < 512; i += 256) { int n = i >> 3, k = i & 7;  int gn = n0g + n; raw[n * 32 + k]      = (gn < NN) ? xf[gn * 8 + k]  : 0.f; }
    for (int i = t; i < 768; i += 256) { int n = i / 12, k = i % 12; int gn = n0g + n; raw[n * 32 + 8 + k]  = (gn < NN) ? xw[gn * 12 + k] : 0.f; }
    for (int i = t; i < 640; i += 256) { int n = i / 10, k = i % 10; int gn = n0g + n; raw[n * 32 + 20 + k] = (gn < NN) ? xt[gn * 10 + k] : 0.f; }
    __syncthreads();

    // stage A: per-node 192-dim encoded features (relu of 3 small matmuls)
    for (int i = t; i < 12288; i += 256) {
        int n = i / 192, c = i % 192;
        int mod = c >> 6, cc = c & 63;
        int koff = (mod == 0) ? 0 : ((mod == 1) ? 8 : 20);
        int kn   = (mod == 0) ? 8 : ((mod == 1) ? 12 : 10);
        const float* wr = Wenc + ((mod == 0) ? 0 : ((mod == 1) ? 512 : 1280));
        float v = Benc[c];
        for (int k = 0; k < kn; k++) v = fmaf(raw[n * 32 + koff + k], wr[k * 64 + cc], v);
        xs[n * 196 + c] = fmaxf(v, 0.f);
    }
    __syncthreads();

    // stage B: 64x64 output tile, 4x4 register micro-tile per thread
    const int cg = t & 15, ng = t >> 4;
    const int n0 = ng * 4, c0 = cg * 4;
    float acc[4][4];
#pragma unroll
    for (int i = 0; i < 4; i++)
#pragma unroll
        for (int j = 0; j < 4; j++) acc[i][j] = 0.f;

#pragma unroll 4
    for (int k = 0; k < 192; k++) {
        float4 b = *(const float4*)&Ws[k * 64 + c0];
#pragma unroll
        for (int i = 0; i < 4; i++) {
            float a = xs[(n0 + i) * 196 + k];
            acc[i][0] = fmaf(a, b.x, acc[i][0]);
            acc[i][1] = fmaf(a, b.y, acc[i][1]);
            acc[i][2] = fmaf(a, b.z, acc[i][2]);
            acc[i][3] = fmaf(a, b.w, acc[i][3]);
        }
    }
#pragma unroll
    for (int i = 0; i < 4; i++) {
        int gn = n0g + n0 + i;
        if (gn < NN) {
            float di = g_dinv[gn];
            float4 o = make_float4(di * acc[i][0], di * acc[i][1], di * acc[i][2], di * acc[i][3]);
            *(float4*)&g_bufA[(size_t)gn * 64 + c0] = o;
        }
    }
}

// ---------------- GCN linear : hs = dinv .* (x @ W) , W is 64x64 ----------------
__global__ void __launch_bounds__(256) k_lin(const float* __restrict__ W, int src_is_A)
{
    __shared__ __align__(16) float Ws[4096];
    __shared__ __align__(16) float xs[64 * 68];
    const float* x = src_is_A ? g_bufA : g_bufB;
    float* out     = src_is_A ? g_bufB : g_bufA;
    const int t = threadIdx.x;
    for (int i = t; i < 4096; i += 256) Ws[i] = W[i];

    const int n0g = blockIdx.x * 64;
    for (int i = t; i < 1024; i += 256) {
        int n = i >> 4, k4 = i & 15;
        int gn = n0g + n;
        float4 v = (gn < NN) ? *(const float4*)&x[(size_t)gn * 64 + k4 * 4] : make_float4(0, 0, 0, 0);
        *(float4*)&xs[n * 68 + k4 * 4] = v;
    }
    __syncthreads();

    const int cg = t & 15, ng = t >> 4;
    const int n0 = ng * 4, c0 = cg * 4;
    float acc[4][4];
#pragma unroll
    for (int i = 0; i < 4; i++)
#pragma unroll
        for (int j = 0; j < 4; j++) acc[i][j] = 0.f;

#pragma unroll 8
    for (int k = 0; k < 64; k++) {
        float4 b = *(const float4*)&Ws[k * 64 + c0];
#pragma unroll
        for (int i = 0; i < 4; i++) {
            float a = xs[(n0 + i) * 68 + k];
            acc[i][0] = fmaf(a, b.x, acc[i][0]);
            acc[i][1] = fmaf(a, b.y, acc[i][1]);
            acc[i][2] = fmaf(a, b.z, acc[i][2]);
            acc[i][3] = fmaf(a, b.w, acc[i][3]);
        }
    }
#pragma unroll
    for (int i = 0; i < 4; i++) {
        int gn = n0g + n0 + i;
        if (gn < NN) {
            float di = g_dinv[gn];
            float4 o = make_float4(di * acc[i][0], di * acc[i][1], di * acc[i][2], di * acc[i][3]);
            *(float4*)&out[(size_t)gn * 64 + c0] = o;
        }
    }
}

// ---------------- gather aggregation : x_out = relu(dinv_i * (sum_j hs_j + hs_i) + b) ----------------
// one warp per node; lane handles 2 feature columns (float2)
__global__ void __launch_bounds__(256) k_gather(int src_is_A, const float* __restrict__ bias)
{
    const float* hs = src_is_A ? g_bufA : g_bufB;
    float* out      = src_is_A ? g_bufB : g_bufA;
    const int node = (blockIdx.x * 256 + threadIdx.x) >> 5;
    if (node >= NN) return;
    const int lane = threadIdx.x & 31;

    const int beg = g_rowptr[node], end = g_rowptr[node + 1];
    float2 acc = *(const float2*)&hs[(size_t)node * 64 + lane * 2];  // self-loop term

    int p = beg;
    for (; p + 32 <= end; p += 32) {
        int idx = g_col[p + lane];
#pragma unroll
        for (int tt = 0; tt < 32; tt++) {
            int j = __shfl_sync(0xffffffffu, idx, tt);
            float2 v = *(const float2*)&hs[(size_t)j * 64 + lane * 2];
            acc.x += v.x; acc.y += v.y;
        }
    }
    if (p < end) {
        int rem = end - p;
        int idx = (lane < rem) ? g_col[p + lane] : 0;
        for (int tt = 0; tt < rem; tt++) {
            int j = __shfl_sync(0xffffffffu, idx, tt);
            float2 v = *(const float2*)&hs[(size_t)j * 64 + lane * 2];
            acc.x += v.x; acc.y += v.y;
        }
    }

    float di = g_dinv[node];
    float bx = __ldg(&bias[lane * 2]), by = __ldg(&bias[lane * 2 + 1]);
    float2 o;
    o.x = fmaxf(fmaf(di, acc.x, bx), 0.f);
    o.y = fmaxf(fmaf(di, acc.y, by), 0.f);
    *(float2*)&out[(size_t)node * 64 + lane * 2] = o;
}

// ---------------- output MLP : out = relu(x @ W1 + b1) @ W2 + b2 ----------------
__global__ void __launch_bounds__(256) k_out(int src_is_A,
    const float* __restrict__ W1, const float* __restrict__ B1,
    const float* __restrict__ W2, const float* __restrict__ B2,
    float* __restrict__ out)
{
    const float* x = src_is_A ? g_bufA : g_bufB;
    __shared__ float W1s[2048];
    __shared__ float W2s[32];
    __shared__ float B1s[32];
    __shared__ float xsh[8][64];
    const int t = threadIdx.x;
    for (int i = t; i < 2048; i += 256) W1s[i] = W1[i];
    if (t < 32) { W2s[t] = W2[t]; B1s[t] = B1[t]; }
    __syncthreads();

    const int lane = t & 31, w = t >> 5;
    const int node = blockIdx.x * 8 + w;
    if (node < NN) {
        xsh[w][lane]      = x[(size_t)node * 64 + lane];
        xsh[w][32 + lane] = x[(size_t)node * 64 + 32 + lane];
        __syncwarp();
        float m = B1s[lane];
#pragma unroll
        for (int k = 0; k < 64; k++) m = fmaf(xsh[w][k], W1s[k * 32 + lane], m);
        m = fmaxf(m, 0.f) * W2s[lane];
#pragma unroll
        for (int off = 16; off; off >>= 1) m += __shfl_xor_sync(0xffffffffu, m, off);
        if (lane == 0) out[node] = m + B2[0];
    }
}

// ---------------- launch ----------------
extern "C" void kernel_launch(void* const* d_in, const int* in_sizes, int n_in,
                              void* d_out, int out_size)
{
    const float* xf  = (const float*)d_in[0];
    const float* xw  = (const float*)d_in[1];
    const float* xt  = (const float*)d_in[2];
    const void*  ei  = d_in[3];
    const float* wf  = (const float*)d_in[4];
    const float* bf  = (const float*)d_in[5];
    const float* ww  = (const float*)d_in[6];
    const float* bw  = (const float*)d_in[7];
    const float* wt  = (const float*)d_in[8];
    const float* bt  = (const float*)d_in[9];
    const float* w0  = (const float*)d_in[10];
    const float* b0  = (const float*)d_in[11];
    const float* w1  = (const float*)d_in[12];
    const float* b1  = (const float*)d_in[13];
    const float* w2  = (const float*)d_in[14];
    const float* b2  = (const float*)d_in[15];
    const float* ow1 = (const float*)d_in[16];
    const float* ob1 = (const float*)d_in[17];
    const float* ow2 = (const float*)d_in[18];
    const float* ob2 = (const float*)d_in[19];
    float* out = (float*)d_out;

    const int ENC_SMEM = (12288 + 1920 + 192 + 12544 + 2048) * 4;  // 115968 B
    cudaFuncSetAttribute(k_enc0, cudaFuncAttributeMaxDynamicSharedMemorySize, ENC_SMEM);

    const int nbScan = (NN + 1023) / 1024;  // 98
    const int tiles  = (NN + 63) / 64;      // 1563
    const int nwarps = (NN + 7) / 8;        // 12500

    // edge dtype detection, then CSR build (by destination) + dinv
    k_detect<<<1, 32>>>((const int*)ei);
    k_zero<<<(NN + 255) / 256, 256>>>();
    k_deg<<<(EE + 255) / 256, 256>>>(ei);
    k_scan1<<<nbScan, 256>>>();
    k_scan2<<<1, 128>>>(nbScan);
    k_scan3<<<nbScan, 256>>>();
    k_fill<<<(EE + 255) / 256, 256>>>(ei);

    // layer 0: fused encoders + linear -> hs0 (A), gather -> x1 (B)
    k_enc0<<<tiles, 256, ENC_SMEM>>>(xf, xw, xt, wf, bf, ww, bw, wt, bt, w0);
    k_gather<<<nwarps, 256>>>(1, b0);
    // layer 1
    k_lin<<<tiles, 256>>>(w1, 0);           // B -> A
    k_gather<<<nwarps, 256>>>(1, b1);       // A -> B
    // layer 2
    k_lin<<<tiles, 256>>>(w2, 0);           // B -> A
    k_gather<<<nwarps, 256>>>(1, b2);       // A -> B
    // output MLP
    k_out<<<nwarps, 256>>>(0, ow1, ob1, ow2, ob2, out);
}